// round 17
// baseline (speedup 1.0000x reference)
#include <cuda_runtime.h>
#include <cstdint>
#include <cuda_fp16.h>
#include <mma.h>
#include <math.h>

using namespace nvcuda;

#define BB 8
#define CC 512
#define HH 64
#define WW 64
#define HW 4096            // HH*WW

// Scratch (allocation-free: __device__ globals).
__device__ __half g_pqh[BB * HW * 64];              // [b, pix, o]  fp16, bias INCLUDED
__device__ __half g_pkh[BB * HW * 64];              // [b, pix, o]  fp16, bias INCLUDED
__device__ __half g_pvh[(size_t)BB * HW * CC];      // [b, pix, c]  fp16 (no bias)
__device__ float  g_att[(size_t)BB * HW * 128];     // [b,h,w, 0:64=attH | 64:128=attW]
__device__ __half g_tmpHh[(size_t)BB * HW * CC];    // [b, w, h, c] fp16
__device__ __half g_vh[(size_t)BB * CC * HW];       // v in fp16, [b, c, pix]
__device__ __half g_Wvh[512 * 512];                 // Wv in fp16, [n, k]

// ---- cp.async helpers -----------------------------------------------------
__device__ __forceinline__ unsigned sptr(const void* p) {
    return (unsigned)__cvta_generic_to_shared(p);
}
__device__ __forceinline__ void cpa16(unsigned s, const void* g) {
    asm volatile("cp.async.cg.shared.global [%0], [%1], 16;\n" :: "r"(s), "l"(g));
}
#define CP_COMMIT() asm volatile("cp.async.commit_group;\n" ::: "memory")
#define CP_WAIT(n)  asm volatile("cp.async.wait_group %0;\n" :: "n"(n) : "memory")

__device__ __forceinline__ uint2 f4_to_h4(float4 f) {
    __half2 h0 = __floats2half2_rn(f.x, f.y);
    __half2 h1 = __floats2half2_rn(f.z, f.w);
    return make_uint2(*(unsigned*)&h0, *(unsigned*)&h1);
}

// ---------------------------------------------------------------------------
// fp32 -> fp16 streaming converts (v, Wv)
// ---------------------------------------------------------------------------
__global__ __launch_bounds__(256) void prep_v(const float* __restrict__ v)
{
    size_t i = ((size_t)blockIdx.x * 256 + threadIdx.x) * 4;
    *(uint2*)(g_vh + i) = f4_to_h4(*(const float4*)(v + i));
}
__global__ __launch_bounds__(256) void prep_w(const float* __restrict__ Wv)
{
    size_t i = ((size_t)blockIdx.x * 256 + threadIdx.x) * 4;
    *(uint2*)(g_Wvh + i) = f4_to_h4(*(const float4*)(Wv + i));
}

// ---------------------------------------------------------------------------
// q/k projection, fp16 HMMA, on-the-fly fp32->fp16, double-buffered smem,
// ONE __syncthreads per K-chunk.
// out_h[b,pix,o] = bias[o] + sum_c W[o,c] * x[b,c,pix]
// ---------------------------------------------------------------------------
__global__ __launch_bounds__(256, 2) void proj_qk(
    const float* __restrict__ q, const float* __restrict__ Wq,
    const float* __restrict__ kk, const float* __restrict__ Wk,
    const float* __restrict__ bq, const float* __restrict__ bk)
{
    extern __shared__ float smf[];
    __half (*As)[64][136] = (__half(*)[64][136])smf;                  // [buf][k][m]
    __half (*Bs)[64][72]  = (__half(*)[64][72])((char*)smf + 2 * 64 * 136 * 2);
    float  (*Osm)[68]     = (float(*)[68])smf;                        // epilogue reuse

    const int t = threadIdx.x;
    const int warp = t >> 5;
    const int wm = warp >> 1;
    const int wn = warp & 1;
    const int mg0 = blockIdx.x * 128;
    const int b = mg0 >> 12;
    const int pix0 = mg0 & 4095;

    const float* x    = blockIdx.y ? kk : q;
    const float* W    = blockIdx.y ? Wk : Wq;
    const float* bias = blockIdx.y ? bk : bq;
    __half* outp      = blockIdx.y ? g_pkh : g_pqh;
    const float* xb = x + (size_t)b * CC * HW + pix0;

    wmma::fragment<wmma::accumulator, 16, 16, 16, float> acc[2][2];
#pragma unroll
    for (int i = 0; i < 2; i++)
#pragma unroll
        for (int j = 0; j < 2; j++) wmma::fill_fragment(acc[i][j], 0.0f);

    float4 ra[8], rb[4];
    auto ldreg = [&](int c0) {
#pragma unroll
        for (int i = 0; i < 8; i++) {
            int idx = t + i * 256;
            int r = idx >> 5, p4 = idx & 31;
            ra[i] = *(const float4*)(xb + (size_t)(c0 + r) * HW + p4 * 4);
        }
#pragma unroll
        for (int i = 0; i < 4; i++) {
            int idx = t + i * 256;
            int n = idx >> 4, k4 = idx & 15;
            rb[i] = *(const float4*)(W + (size_t)n * CC + c0 + k4 * 4);
        }
    };
    auto stcvt = [&](int buf) {
#pragma unroll
        for (int i = 0; i < 8; i++) {
            int idx = t + i * 256;
            int r = idx >> 5, p4 = idx & 31;
            *(uint2*)&As[buf][r][p4 * 4] = f4_to_h4(ra[i]);
        }
#pragma unroll
        for (int i = 0; i < 4; i++) {
            int idx = t + i * 256;
            int n = idx >> 4, k4 = idx & 15;
            *(uint2*)&Bs[buf][n][k4 * 4] = f4_to_h4(rb[i]);
        }
    };

    ldreg(0);
    stcvt(0);
    for (int ch = 0; ch < 8; ch++) {
        const int cur = ch & 1;
        if (ch < 7) ldreg((ch + 1) * 64);      // LDGs issued early, overlap barrier+MMA
        __syncthreads();                        // buf cur visible to all warps
#pragma unroll
        for (int ks = 0; ks < 4; ks++) {
            wmma::fragment<wmma::matrix_a, 16, 16, 16, __half, wmma::col_major> a[2];
            wmma::load_matrix_sync(a[0], &As[cur][ks * 16][wm * 32], 136);
            wmma::load_matrix_sync(a[1], &As[cur][ks * 16][wm * 32 + 16], 136);
            wmma::fragment<wmma::matrix_b, 16, 16, 16, __half, wmma::col_major> bf[2];
            wmma::load_matrix_sync(bf[0], &Bs[cur][wn * 32][ks * 16], 72);
            wmma::load_matrix_sync(bf[1], &Bs[cur][wn * 32 + 16][ks * 16], 72);
#pragma unroll
            for (int i = 0; i < 2; i++)
#pragma unroll
                for (int j = 0; j < 2; j++)
                    wmma::mma_sync(acc[i][j], a[i], bf[j], acc[i][j]);
        }
        if (ch < 7) stcvt(cur ^ 1);             // write OTHER buffer; safe before next sync
    }
    __syncthreads();                            // mainloop reads done before Osm aliases As

#pragma unroll
    for (int i = 0; i < 2; i++)
#pragma unroll
        for (int j = 0; j < 2; j++)
            wmma::store_matrix_sync(&Osm[wm * 32 + i * 16][wn * 32 + j * 16],
                                    acc[i][j], 68, wmma::mem_row_major);
    __syncthreads();
#pragma unroll
    for (int i = 0; i < 8; i++) {
        int idx = t + i * 256;
        int pix = idx >> 4, o4 = idx & 15;
        float4 f = *(float4*)&Osm[pix][o4 * 4];
        f.x += bias[o4 * 4 + 0]; f.y += bias[o4 * 4 + 1];
        f.z += bias[o4 * 4 + 2]; f.w += bias[o4 * 4 + 3];
        *(uint2*)(outp + (size_t)(mg0 + pix) * 64 + o4 * 4) = f4_to_h4(f);
    }
}

// ---------------------------------------------------------------------------
// v projection, fp16 HMMA, 3-stage cp.async pipeline, ONE sync per K-chunk.
// pvh[b,pix,n] = sum_c v[b,c,pix] * Wv[n,c]
// ---------------------------------------------------------------------------
__global__ __launch_bounds__(256, 2) void proj_pv()
{
    extern __shared__ float smf[];
    __half (*As)[64][136] = (__half(*)[64][136])smf;                 // [3][k][m]
    __half (*Bs)[128][72] = (__half(*)[128][72])((char*)smf + 3 * 64 * 136 * 2);
    float  (*Osm)[132]    = (float(*)[132])smf;                      // epilogue reuse

    const int t = threadIdx.x;
    const int warp = t >> 5;
    const int wm = warp >> 2;
    const int wn = warp & 3;
    const int nt = blockIdx.x;
    const int mg0 = blockIdx.y * 128;
    const int b = mg0 >> 12;
    const int pix0 = mg0 & 4095;

    const __half* xb = g_vh + (size_t)b * CC * HW + pix0;
    const __half* Wb = g_Wvh + (size_t)(nt * 128) * 512;

    wmma::fragment<wmma::accumulator, 16, 16, 16, float> acc[4][2];
#pragma unroll
    for (int i = 0; i < 4; i++)
#pragma unroll
        for (int j = 0; j < 2; j++) wmma::fill_fragment(acc[i][j], 0.0f);

    auto stage = [&](int buf, int c0) {
#pragma unroll
        for (int i = 0; i < 4; i++) {
            int idx = t + i * 256;
            int r = idx >> 4, s = idx & 15;
            cpa16(sptr(&As[buf][r][s * 8]), xb + (size_t)(c0 + r) * HW + s * 8);
        }
#pragma unroll
        for (int i = 0; i < 4; i++) {
            int idx = t + i * 256;
            int n = idx >> 3, s = idx & 7;
            cpa16(sptr(&Bs[buf][n][s * 8]), Wb + (size_t)n * 512 + c0 + s * 8);
        }
        CP_COMMIT();
    };

    stage(0, 0);
    stage(1, 64);
    for (int kc = 0; kc < 8; kc++) {
        const int cur = kc % 3;
        if (kc < 7) { CP_WAIT(1); }             // chunk kc complete
        else        { CP_WAIT(0); }
        __syncthreads();                        // all warps past mma(kc-1)
        if (kc < 6) stage((kc + 2) % 3, (kc + 2) * 64);  // overlaps this chunk's MMA
#pragma unroll
        for (int ks = 0; ks < 4; ks++) {
            wmma::fragment<wmma::matrix_a, 16, 16, 16, __half, wmma::col_major> a[4];
#pragma unroll
            for (int i = 0; i < 4; i++)
                wmma::load_matrix_sync(a[i], &As[cur][ks * 16][wm * 64 + i * 16], 136);
            wmma::fragment<wmma::matrix_b, 16, 16, 16, __half, wmma::col_major> bf[2];
#pragma unroll
            for (int j = 0; j < 2; j++)
                wmma::load_matrix_sync(bf[j], &Bs[cur][wn * 32 + j * 16][ks * 16], 72);
#pragma unroll
            for (int i = 0; i < 4; i++)
#pragma unroll
                for (int j = 0; j < 2; j++)
                    wmma::mma_sync(acc[i][j], a[i], bf[j], acc[i][j]);
        }
    }
    __syncthreads();                            // mainloop done before Osm aliases As

#pragma unroll
    for (int i = 0; i < 4; i++)
#pragma unroll
        for (int j = 0; j < 2; j++)
            wmma::store_matrix_sync(&Osm[wm * 64 + i * 16][wn * 32 + j * 16],
                                    acc[i][j], 132, wmma::mem_row_major);
    __syncthreads();
#pragma unroll
    for (int i = 0; i < 16; i++) {
        int idx = t + i * 256;
        int row = idx >> 5, c4 = idx & 31;
        float4 f = *(float4*)&Osm[row][c4 * 4];
        *(uint2*)(g_pvh + (size_t)(mg0 + row) * CC + nt * 128 + c4 * 4) = f4_to_h4(f);
    }
}

// ---------------------------------------------------------------------------
// Attention scores, fp16 WMMA (pq/pk fp16, bias included).
// ---------------------------------------------------------------------------
__global__ __launch_bounds__(256) void scores_h()
{
    __shared__ __half As[64][72];
    __shared__ __half Bs[64][72];
    __shared__ float  Osm[64][68];
    const int t = threadIdx.x;
    const int warp = t >> 5;
    const int q = blockIdx.x;
    const int b = blockIdx.y;
    const int mode = blockIdx.z;

    size_t base; int rs;
    if (mode == 0) { base = ((size_t)b * HW + q) * 64;      rs = 64 * 64; }
    else           { base = ((size_t)b * HW + q * 64) * 64; rs = 64;      }

#pragma unroll
    for (int i = 0; i < 2; i++) {
        int idx = t + i * 256;
        int r = idx >> 3, s = idx & 7;
        cpa16(sptr(&As[r][s * 8]), g_pqh + base + (size_t)r * rs + s * 8);
        cpa16(sptr(&Bs[r][s * 8]), g_pkh + base + (size_t)r * rs + s * 8);
    }
    CP_COMMIT(); CP_WAIT(0);
    __syncthreads();

#pragma unroll
    for (int j = 0; j < 2; j++) {
        int tile = warp + j * 8;
        int tr = (tile & 3) * 16, tc = (tile >> 2) * 16;
        wmma::fragment<wmma::accumulator, 16, 16, 16, float> acc;
        wmma::fill_fragment(acc, 0.0f);
#pragma unroll
        for (int ks = 0; ks < 4; ks++) {
            wmma::fragment<wmma::matrix_a, 16, 16, 16, __half, wmma::row_major> a;
            wmma::load_matrix_sync(a, &As[tr][ks * 16], 72);
            wmma::fragment<wmma::matrix_b, 16, 16, 16, __half, wmma::col_major> bf;
            wmma::load_matrix_sync(bf, &Bs[tc][ks * 16], 72);
            wmma::mma_sync(acc, a, bf, acc);
        }
        wmma::store_matrix_sync(&Osm[tr][tc], acc, 68, wmma::mem_row_major);
    }
    __syncthreads();

#pragma unroll
    for (int i = 0; i < 16; i++) {
        int idx = t + i * 256;
        int r = idx >> 6, c = idx & 63;
        float v = Osm[r][c];
        size_t o;
        if (mode == 0) {
            if (r == c) v = -1e30f;
            o = (((size_t)b * HH + r) * WW + q) * 128 + c;
        } else {
            o = (((size_t)b * HH + q) * WW + r) * 128 + 64 + c;
        }
        g_att[o] = v;
    }
}

// ---------------------------------------------------------------------------
// Softmax over 128 concatenated logits; one warp per row.
// ---------------------------------------------------------------------------
__global__ __launch_bounds__(256) void softmax_kernel()
{
    const int r    = (blockIdx.x * 256 + threadIdx.x) >> 5;
    const int lane = threadIdx.x & 31;
    float4* row = (float4*)(g_att + (size_t)r * 128);
    float4 v = row[lane];
    float m = fmaxf(fmaxf(v.x, v.y), fmaxf(v.z, v.w));
#pragma unroll
    for (int o = 16; o > 0; o >>= 1) m = fmaxf(m, __shfl_xor_sync(0xffffffffu, m, o));
    v.x = __expf(v.x - m); v.y = __expf(v.y - m);
    v.z = __expf(v.z - m); v.w = __expf(v.w - m);
    float s = v.x + v.y + v.z + v.w;
#pragma unroll
    for (int o = 16; o > 0; o >>= 1) s += __shfl_xor_sync(0xffffffffu, s, o);
    float inv = 1.0f / s;
    v.x *= inv; v.y *= inv; v.z *= inv; v.w *= inv;
    row[lane] = v;
}

// ---------------------------------------------------------------------------
// tmpH[b,w,h,c] = sum_g attH[b,h,w,g] * pvh[b,pix(g,w),c]   (fp16 MMA, fp16 out)
// ---------------------------------------------------------------------------
__global__ __launch_bounds__(256, 2) void tmph_h()
{
    extern __shared__ float smf[];
    __half (*Att)[72]     = (__half(*)[72])smf;                       // [h][g]
    __half (*Ps)[64][136] = (__half(*)[64][136])((char*)smf + 64 * 72 * 2);
    float  (*OsmT)[132]   = (float(*)[132])((char*)smf + 64 * 72 * 2 + 2 * 64 * 136 * 2);
    const int t = threadIdx.x, w = blockIdx.x, b = blockIdx.y;
    const int warp = t >> 5;
    const int wh = warp >> 1;
    const int wc = warp & 1;

    auto stage = [&](int buf, int c0) {
#pragma unroll
        for (int i = 0; i < 4; i++) {
            int idx = t + i * 256;
            int g = idx >> 4, s = idx & 15;
            cpa16(sptr(&Ps[buf][g][s * 8]),
                  g_pvh + ((size_t)b * HW + g * WW + w) * CC + c0 + s * 8);
        }
        CP_COMMIT();
    };

    stage(0, 0);
#pragma unroll
    for (int i = 0; i < 4; i++) {
        int idx = t + i * 256;
        int h = idx >> 4, g4 = idx & 15;
        float4 f = *(const float4*)(g_att + (((size_t)b * HH + h) * WW + w) * 128 + g4 * 4);
        *(uint2*)&Att[h][g4 * 4] = f4_to_h4(f);
    }

    for (int kc = 0; kc < 4; kc++) {
        const int cur = kc & 1;
        const int c0 = kc * 128;
        if (kc < 3) { stage(cur ^ 1, c0 + 128); CP_WAIT(1); }
        else        { CP_WAIT(0); }
        __syncthreads();

        wmma::fragment<wmma::accumulator, 16, 16, 16, float> acc[4];
#pragma unroll
        for (int i = 0; i < 4; i++) wmma::fill_fragment(acc[i], 0.0f);
#pragma unroll
        for (int ks = 0; ks < 4; ks++) {
            wmma::fragment<wmma::matrix_a, 16, 16, 16, __half, wmma::row_major> a;
            wmma::load_matrix_sync(a, &Att[wh * 16][ks * 16], 72);
#pragma unroll
            for (int ci = 0; ci < 4; ci++) {
                wmma::fragment<wmma::matrix_b, 16, 16, 16, __half, wmma::row_major> bf;
                wmma::load_matrix_sync(bf, &Ps[cur][ks * 16][wc * 64 + ci * 16], 136);
                wmma::mma_sync(acc[ci], a, bf, acc[ci]);
            }
        }
#pragma unroll
        for (int ci = 0; ci < 4; ci++)
            wmma::store_matrix_sync(&OsmT[wh * 16][wc * 64 + ci * 16], acc[ci], 132,
                                    wmma::mem_row_major);
        __syncthreads();
#pragma unroll
        for (int i = 0; i < 8; i++) {
            int idx = t + i * 256;
            int row = idx >> 5, c4 = idx & 31;
            float4 f = *(float4*)&OsmT[row][c4 * 4];
            *(uint2*)(g_tmpHh + (((size_t)b * WW + w) * HH + row) * CC + c0 + c4 * 4) =
                f4_to_h4(f);
        }
        __syncthreads();
    }
}

// ---------------------------------------------------------------------------
// Final per (b,h): Sw[w][c] = sum_f attW[b,h,w,f] * pvh[b,pix(h,f),c] (fp16 MMA)
// out[b,c,h,w] = vh[b,c,h,w] + gamma * (Sw + tmpHh[b,w,h,c] + bv[c])
// (value read from fp16 g_vh — halves the dominant read traffic)
// ---------------------------------------------------------------------------
__global__ __launch_bounds__(256, 2) void final_h(
    const float* __restrict__ bv, const float* __restrict__ gamma,
    float* __restrict__ out)
{
    extern __shared__ float smf[];
    __half (*Att)[72]     = (__half(*)[72])smf;                        // [w][f]
    __half (*Ps)[64][136] = (__half(*)[64][136])((char*)smf + 64 * 72 * 2);
    float  (*Osm)[132]    = (float(*)[132])((char*)smf + 64 * 72 * 2 + 2 * 64 * 136 * 2);
    const int t = threadIdx.x, h = blockIdx.x, b = blockIdx.y;
    const int warp = t >> 5;
    const int ww = warp >> 1;
    const int wc = warp & 1;
    const float gm = gamma[0];

    auto stage = [&](int buf, int c0) {
#pragma unroll
        for (int i = 0; i < 4; i++) {
            int idx = t + i * 256;
            int f = idx >> 4, s = idx & 15;
            cpa16(sptr(&Ps[buf][f][s * 8]),
                  g_pvh + ((size_t)b * HW + h * WW + f) * CC + c0 + s * 8);
        }
        CP_COMMIT();
    };

    stage(0, 0);
#pragma unroll
    for (int i = 0; i < 4; i++) {
        int idx = t + i * 256;
        int w = idx >> 4, f4 = idx & 15;
        float4 f = *(const float4*)(
            g_att + (((size_t)b * HH + h) * WW + w) * 128 + 64 + f4 * 4);
        *(uint2*)&Att[w][f4 * 4] = f4_to_h4(f);
    }

    const int w4 = t & 15;          // epilogue: 4 consecutive w
    const int cB = t >> 4;          // epilogue: 8 consecutive c

    for (int kc = 0; kc < 4; kc++) {
        const int cur = kc & 1;
        const int c0 = kc * 128;
        if (kc < 3) { stage(cur ^ 1, c0 + 128); CP_WAIT(1); }
        else        { CP_WAIT(0); }
        __syncthreads();

        wmma::fragment<wmma::accumulator, 16, 16, 16, float> acc[4];
#pragma unroll
        for (int i = 0; i < 4; i++) wmma::fill_fragment(acc[i], 0.0f);
#pragma unroll
        for (int ks = 0; ks < 4; ks++) {
            wmma::fragment<wmma::matrix_a, 16, 16, 16, __half, wmma::row_major> a;
            wmma::load_matrix_sync(a, &Att[ww * 16][ks * 16], 72);
#pragma unroll
            for (int ci = 0; ci < 4; ci++) {
                wmma::fragment<wmma::matrix_b, 16, 16, 16, __half, wmma::row_major> bf;
                wmma::load_matrix_sync(bf, &Ps[cur][ks * 16][wc * 64 + ci * 16], 136);
                wmma::mma_sync(acc[ci], a, bf, acc[ci]);
            }
        }
#pragma unroll
        for (int ci = 0; ci < 4; ci++)
            wmma::store_matrix_sync(&Osm[ww * 16][wc * 64 + ci * 16], acc[ci], 132,
                                    wmma::mem_row_major);
        __syncthreads();

        float th[4][8];
#pragma unroll
        for (int wi = 0; wi < 4; wi++) {
            const __half* tp = g_tmpHh +
                (((size_t)b * WW + w4 * 4 + wi) * HH + h) * CC + c0 + cB * 8;
            uint4 u = *(const uint4*)tp;
            __half2* hp = (__half2*)&u;
#pragma unroll
            for (int k = 0; k < 4; k++) {
                float2 f2 = __half22float2(hp[k]);
                th[wi][k * 2 + 0] = f2.x;
                th[wi][k * 2 + 1] = f2.y;
            }
        }
#pragma unroll
        for (int ci = 0; ci < 8; ci++) {
            int c = c0 + cB * 8 + ci;
            float bvv = bv[c];
            size_t vbase = (((size_t)b * CC + c) * HH + h) * WW;
            uint2 vu = *(const uint2*)(g_vh + vbase + w4 * 4);
            __half2* vh2 = (__half2*)&vu;
            float2 v01 = __half22float2(vh2[0]);
            float2 v23 = __half22float2(vh2[1]);
            float4 ov;
            ov.x = v01.x + gm * (Osm[w4 * 4 + 0][cB * 8 + ci] + th[0][ci] + bvv);
            ov.y = v01.y + gm * (Osm[w4 * 4 + 1][cB * 8 + ci] + th[1][ci] + bvv);
            ov.z = v23.x + gm * (Osm[w4 * 4 + 2][cB * 8 + ci] + th[2][ci] + bvv);
            ov.w = v23.y + gm * (Osm[w4 * 4 + 3][cB * 8 + ci] + th[3][ci] + bvv);
            ((float4*)(out + vbase))[w4] = ov;
        }
        __syncthreads();
    }
}

// ---------------------------------------------------------------------------
#define SMEM_QK  (2 * 64 * 136 * 2 + 2 * 64 * 72 * 2)                 // 53248 (>= Osm 34816)
#define SMEM_PV  (3 * 64 * 136 * 2 + 3 * 128 * 72 * 2)                // 107520 (>= Osm 67584)
#define SMEM_TH  (64 * 72 * 2 + 2 * 64 * 136 * 2 + 64 * 132 * 4)      // 77824
#define SMEM_FN  (64 * 72 * 2 + 2 * 64 * 136 * 2 + 64 * 132 * 4)      // 77824

extern "C" void kernel_launch(void* const* d_in, const int* in_sizes, int n_in,
                              void* d_out, int out_size)
{
    (void)in_sizes; (void)n_in; (void)out_size;
    const float* query = (const float*)d_in[0];
    const float* key_t = (const float*)d_in[1];
    const float* value = (const float*)d_in[2];
    const float* Wq    = (const float*)d_in[3];
    const float* bq    = (const float*)d_in[4];
    const float* Wk    = (const float*)d_in[5];
    const float* bk    = (const float*)d_in[6];
    const float* Wv    = (const float*)d_in[7];
    const float* bv    = (const float*)d_in[8];
    const float* gamma = (const float*)d_in[9];
    float* out = (float*)d_out;

    cudaFuncSetAttribute(proj_qk, cudaFuncAttributeMaxDynamicSharedMemorySize, SMEM_QK);
    cudaFuncSetAttribute(proj_pv, cudaFuncAttributeMaxDynamicSharedMemorySize, SMEM_PV);
    cudaFuncSetAttribute(tmph_h,  cudaFuncAttributeMaxDynamicSharedMemorySize, SMEM_TH);
    cudaFuncSetAttribute(final_h, cudaFuncAttributeMaxDynamicSharedMemorySize, SMEM_FN);

    // Slot 4 (ncu-captured) = the new 3-stage proj_pv.
    prep_v<<<16384, 256>>>(value);                                          // 1
    prep_w<<<256, 256>>>(Wv);                                               // 2
    proj_qk<<<dim3(256, 2), 256, SMEM_QK>>>(query, Wq, key_t, Wk, bq, bk);  // 3
    proj_pv<<<dim3(4, 256), 256, SMEM_PV>>>();                              // 4 <- profiled
    scores_h<<<dim3(64, BB, 2), 256>>>();                                   // 5
    softmax_kernel<<<4096, 256>>>();                                        // 6
    tmph_h<<<dim3(WW, BB), 256, SMEM_TH>>>();                               // 7
    final_h<<<dim3(HH, BB), 256, SMEM_FN>>>(bv, gamma, out);                // 8
}